// round 6
// baseline (speedup 1.0000x reference)
#include <cuda_runtime.h>
#include <stdint.h>

#define NN    200
#define HH    20
#define TB    400
#define OUTD  64
#define HP    201
#define NTH   448
#define NP    224        // P threads: tid<NP ; V threads: tid>=NP
#define K0    12         // unrolled zero-delay CSR slots
#define X0    32         // zero-delay spill capacity (global, ~0-2 nodes)
#define K1    48         // delay==1 capacity
#define P2SLOT 224       // padded D>=2 entries per row (7 per lane)
#define CLU   8

// smem: hist 64*201 + 8 double arrays of 208
#define SMEM_FLOATS (64*HP + 8*2*208)
#define SMEM_BYTES  (SMEM_FLOATS * 4)

// ---------------- device scratch ----------------
__device__ __align__(16) float g_tin[(TB*HH + 4)*NN];   // (t,k,n) + pad
__device__ __align__(16) float g_tnz[(TB*HH + 4)*NN];
__device__ float g_wl [NN*NN];
__device__ float g_w0 [NN*K0];
__device__ int   g_o0 [NN*K0];
__device__ uint2 g_x0 [NN*X0];    __device__ int g_x0c[NN];
__device__ uint2 g_e1 [NN*K1];    __device__ int g_e1c[NN];
__device__ uint2 g_p2 [NN*P2SLOT];
__device__ float g_rowsum[NN];
__device__ float g_lm1[OUTD*NN];
__device__ float g_lmt[OUTD*NN];

// ---------------- cluster / mbarrier helpers ----------------
__device__ __forceinline__ uint32_t smem_u32(const void* p) {
    uint32_t a;
    asm("{ .reg .u64 t; cvta.to.shared.u64 t, %1; cvt.u32.u64 %0, t; }" : "=r"(a) : "l"(p));
    return a;
}
__device__ __forceinline__ uint32_t ctarank() {
    uint32_t r; asm("mov.u32 %0, %%cluster_ctarank;" : "=r"(r)); return r;
}
__device__ __forceinline__ void mbar_init(uint32_t a, uint32_t cnt) {
    asm volatile("mbarrier.init.shared.b64 [%0], %1;" :: "r"(a), "r"(cnt) : "memory");
}
__device__ __forceinline__ void fence_cluster() {
    asm volatile("fence.acq_rel.cluster;" ::: "memory");
}
__device__ __forceinline__ void mbar_wait_cl(uint32_t mbar, uint32_t parity) {
    asm volatile(
        "{\n\t.reg .pred P;\n"
        "W%=:\n\t"
        "mbarrier.try_wait.parity.acquire.cluster.shared::cta.b64 P, [%0], %1, 0x989680;\n\t"
        "@P bra.uni D%=;\n\t"
        "bra.uni W%=;\n"
        "D%=:\n\t}"
        :: "r"(mbar), "r"(parity) : "memory");
}
__device__ __forceinline__ void mbar_arrive_rk(uint32_t mbar_local, uint32_t rk) {
    uint32_t rem;
    asm volatile("mapa.shared::cluster.u32 %0, %1, %2;" : "=r"(rem) : "r"(mbar_local), "r"(rk));
    asm volatile("mbarrier.arrive.release.cluster.shared::cluster.b64 _, [%0];" :: "r"(rem) : "memory");
}
__device__ __forceinline__ void st_rk_f32(uint32_t local, uint32_t rk, float v) {
    uint32_t rem;
    asm volatile("mapa.shared::cluster.u32 %0, %1, %2;" : "=r"(rem) : "r"(local), "r"(rk));
    asm volatile("st.shared::cluster.f32 [%0], %1;" :: "r"(rem), "f"(v) : "memory");
}
#define CLUSTER_SYNC() do { \
    asm volatile("barrier.cluster.arrive.aligned;" ::: "memory"); \
    asm volatile("barrier.cluster.wait.aligned;"  ::: "memory"); \
} while (0)

// ---------------- math helpers ----------------
__device__ __forceinline__ float padeth(float y) {     // tanh, |y|<=3
    float z = y * y;
    float num = y * fmaf(z, fmaf(z, 21.0f, 1260.0f), 10395.0f);
    float den = fmaf(z, fmaf(z, fmaf(z, 1.0f, 210.0f), 4725.0f), 10395.0f);
    return __fdividef(num, den);
}
__device__ __forceinline__ float satp(float x) {        // 1000*tanh(x/1000), |x|<=2100 by algebra
    return 1000.0f * padeth(x * 0.001f);
}
__device__ __forceinline__ float tanh_tiny(float y) {   // |y| <= 0.01
    return y * fmaf(-0.33333334f, y * y, 1.0f);
}
__device__ __forceinline__ float tanh_big(float y) {
    float a = fabsf(y);
    float e = __expf(2.0f * a);
    float t = __fdividef(e - 1.0f, e + 1.0f);
    t = (a > 15.0f) ? 1.0f : t;
    return copysignf(t, y);
}
__device__ __forceinline__ float sigf(float x) {
    float e = __expf(0.56f * (6.0f - x));
    return __fdividef(5.0f, 1.0f + e);
}

// ---------------- transpose ----------------
__global__ void k_trans(const float* __restrict__ in, const float* __restrict__ nz) {
    int idx = blockIdx.x * blockDim.x + threadIdx.x;
    if (idx >= TB*HH*NN) return;
    int t = idx % TB;
    int k = (idx / TB) % HH;
    int n = idx / (TB * HH);
    int dst = (t*HH + k)*NN + n;
    g_tin[dst] = in[idx];
    g_tnz[dst] = nz[idx * 3];
}

// ---------------- precompute ----------------
__global__ void k_pre(const float* __restrict__ wbb, const float* __restrict__ sc,
                      const int* __restrict__ dist, const float* __restrict__ lm) {
    __shared__ double red[256];
    int tid = threadIdx.x;
    double acc = 0.0;
    for (int idx = tid; idx < NN*NN; idx += 256) {
        int i = idx / NN, j = idx % NN;
        float w1 = expf(wbb[idx])      * sc[idx];
        float w2 = expf(wbb[j*NN + i]) * sc[j*NN + i];
        float wl = log1pf(0.5f * (w1 + w2));
        g_wl[idx] = wl;
        acc += (double)wl * (double)wl;
    }
    red[tid] = acc; __syncthreads();
    for (int s = 128; s; s >>= 1) { if (tid < s) red[tid] += red[tid + s]; __syncthreads(); }
    float inv = (float)(1.0 / sqrt(red[0]));

    if (tid < NN) {
        int i = tid;
        float rs = 0.0f;
        int c0 = 0, cx = 0, c1 = 0, c2 = 0;
        for (int j = 0; j < NN; ++j) {
            float wn = g_wl[i*NN + j] * inv;
            rs += wn;
            int d = dist[j*NN + i] >> 1;    // trunc(dist/2.0)
            if (d == 0) {
                if (c0 < K0) { g_w0[i*K0 + c0] = wn; g_o0[i*K0 + c0] = j; c0++; }
                else if (cx < X0) { g_x0[i*X0 + cx] = make_uint2(__float_as_uint(wn), (unsigned)j); cx++; }
            } else if (d == 1) {
                if (c1 < K1) { g_e1[i*K1 + c1] = make_uint2(__float_as_uint(wn), (unsigned)j); c1++; }
            } else {
                g_p2[i*P2SLOT + c2] = make_uint2(__float_as_uint(wn), ((unsigned)d << 16) | (unsigned)j); c2++;
            }
        }
        for (; c0 < K0; ++c0) { g_w0[i*K0 + c0] = 0.0f; g_o0[i*K0 + c0] = 0; }
        for (; c2 < P2SLOT; ++c2) g_p2[i*P2SLOT + c2] = make_uint2(0u, (2u << 16));
        g_x0c[i] = cx; g_e1c[i] = c1; g_rowsum[i] = rs;
    }
    __syncthreads();
    if (tid < OUTD) {
        float s = 0.0f;
        for (int j = 0; j < NN; ++j) s += fabsf(lm[tid*NN + j]);
        float invs = 1.0f / s;
        for (int j = 0; j < NN; ++j) g_lm1[tid*NN + j] = lm[tid*NN + j] * invs;
    }
    __syncthreads();
    if (tid < NN) {
        float cs = 0.0f;
        for (int o = 0; o < OUTD; ++o) cs += g_lm1[o*NN + tid];
        cs *= (1.0f / OUTD);
        for (int o = 0; o < OUTD; ++o) g_lmt[o*NN + tid] = g_lm1[o*NN + tid] - cs;
    }
}

// ---------------- main: 8-CTA cluster, rank0 P/V split ----------------
__global__ __launch_bounds__(NTH, 1) __cluster_dims__(CLU, 1, 1)
void k_main(const float* __restrict__ hx, const float* __restrict__ hE,
            float* __restrict__ out)
{
    extern __shared__ float sm[];
    float* hist  = sm;                  // [64][HP]
    float* Mbuf  = hist + 64*HP;        // [2][208]  M for zero-delay gather
    float* E_s   = Mbuf  + 2*208;       // [2][208]  E state (P->V)
    float* sM_s  = E_s   + 2*208;       // [2][208]  500*tanh(rM/500) (P->V)
    float* sgM_s = sM_s  + 2*208;       // [2][208]  sigf(135.01*M)   (P->V)
    float* Mv_s  = sgM_s + 2*208;       // [2][208]  Mv (V->P)
    float* Ev_s  = Mv_s  + 2*208;       // [2][208]  Ev (V->P)
    float* b2    = Ev_s  + 2*208;       // [2][208]  D>=2 coupling
    float* emi   = b2    + 2*208;       // [2][208]  E-I (on rank1)
    __shared__ __align__(8) unsigned long long s_mb[3];

    int tid = threadIdx.x;
    uint32_t rank = ctarank();
    uint32_t mbB  = smem_u32(&s_mb[0]);
    uint32_t mbH0 = smem_u32(&s_mb[1]);
    uint32_t mbH1 = smem_u32(&s_mb[2]);

    // ---- init ----
    for (int s = tid; s < 64*HP; s += NTH) hist[s] = 0.0f;
    __syncthreads();
    if (tid < NN) {
        for (int k = 1; k <= 49; ++k)
            hist[((0 - k) & 63)*HP + tid] = hE[tid*500 + k];
    }
    if (tid == 0) {
        mbar_init(mbB, 7);
        mbar_init(mbH0, 1);
        mbar_init(mbH1, 1);
    }

    if (rank == 0) {
        bool isP = tid < NP;
        int n = isP ? tid : tid - NP;
        bool act = n < NN;

        // ---------- P state ----------
        float M=0,E=0,I=0,Iv=0,sI=0;
        // ---------- V state ----------
        float Mv=0,Ev=0,rs=0,M0=0;
        float w0[K0]; int o0[K0];
        int xc=0, e1c=0;
        float uu[4]={0,0,0,0}, zz[4]={0,0,0,0};
        const float *up = g_tin + 3*NN, *zp = g_tnz + 3*NN;

        if (act) {
            if (isP) {
                M = hx[n*6+0]; E = hx[n*6+1]; I = hx[n*6+2]; Iv = hx[n*6+5];
                Mbuf[n]  = hE[n*500];         // hEb[:,0] initial (parity 0)
                E_s[n]   = E;
                float rM = sigf(E - I);
                sM_s[n]  = 500.0f * tanh_tiny(rM * 0.002f);
                sgM_s[n] = sigf(135.01f * M);
                float rI = 33.76f * sigf(33.76f * M);
                sI = 500.0f * padeth(rI * 0.002f);
            } else {
                Mv = hx[n*6+3]; Ev = hx[n*6+4]; M0 = hx[n*6+0];
                Mv_s[n] = Mv; Ev_s[n] = Ev;
                rs = g_rowsum[n]; xc = g_x0c[n]; e1c = g_e1c[n];
                #pragma unroll
                for (int e = 0; e < K0; ++e) { w0[e] = g_w0[n*K0 + e]; o0[e] = g_o0[n*K0 + e]; }
                #pragma unroll
                for (int i = 0; i < 3; ++i) { uu[i] = g_tin[i*NN + n]; zz[i] = g_tnz[i*NN + n]; }
                up += n; zp += n;
            }
        }
        __syncthreads();
        CLUSTER_SYNC();

        for (int t = 0; t < TB; ++t) {
            mbar_wait_cl(mbB, (uint32_t)(t & 1));
            float base = 0.0f;
            if (!isP && act) {
                base = b2[(t & 1)*208 + n];
                int sl = ((t - 1) & 63)*HP;
                const uint2* e1 = g_e1 + n*K1;
                for (int e = 0; e < e1c; ++e) {
                    uint2 v = e1[e];
                    base = fmaf(__uint_as_float(v.x), hist[sl + (int)v.y], base);
                }
            }

            #pragma unroll 2
            for (int k = 0; k < HH; ++k) {
                int p = (k & 1)*208, q = ((k & 1) ^ 1)*208;
                if (act) {
                    if (isP) {
                        float Mvv = Mv_s[p + n];
                        float Evv = Ev_s[p + n];
                        float mnew = satp(fmaf(1e-4f, Mvv, M));
                        float En   = satp(fmaf(1e-4f, Evv, E));
                        float In   = satp(fmaf(1e-4f, Iv,  I));
                        float Ivn  = satp(fmaf(1e-4f, fmaf(1122.0f, sI, fmaf(-102.0f, Iv, -2601.0f*I)), Iv));
                        Mbuf[q + n] = mnew;
                        E_s [q + n] = En;
                        float rM  = sigf(En - In);
                        float sMn = 500.0f * tanh_tiny(rM * 0.002f);
                        float sgn = sigf(135.01f * mnew);
                        float rI  = 33.76f * sigf(33.76f * mnew);
                        sI = 500.0f * padeth(rI * 0.002f);
                        sM_s [q + n] = sMn;
                        sgM_s[q + n] = sgn;
                        M = mnew; E = En; I = In; Iv = Ivn;
                    } else {
                        uu[(k + 3) & 3] = up[0]; zz[(k + 3) & 3] = zp[0];
                        up += NN; zp += NN;
                        const float* rd = Mbuf + p;
                        float Mo  = ((t | k) == 0) ? M0 : rd[n];
                        float Eo  = E_s  [p + n];
                        float sMo = sM_s [p + n];
                        float sgo = sgM_s[p + n];
                        float l0 = base, l1 = 0.0f, l2 = 0.0f, l3 = 0.0f;
                        #pragma unroll
                        for (int e = 0; e < K0; e += 4) {
                            l0 = fmaf(w0[e+0], rd[o0[e+0]], l0);
                            l1 = fmaf(w0[e+1], rd[o0[e+1]], l1);
                            l2 = fmaf(w0[e+2], rd[o0[e+2]], l2);
                            l3 = fmaf(w0[e+3], rd[o0[e+3]], l3);
                        }
                        float led = (l0 + l1) + (l2 + l3);
                        if (xc) {
                            const uint2* xp = g_x0 + n*X0;
                            for (int e = 0; e < xc; ++e) {
                                uint2 v = xp[e];
                                led = fmaf(__uint_as_float(v.x), rd[(int)v.y], led);
                            }
                        }
                        float u = uu[k & 3], z = zz[k & 3];
                        float rE  = fmaf(250.0f, z, fmaf(1000.01f, led - rs*Eo, 108.01f * sgo));
                        float sE  = 500.0f * tanh_big(rE * 0.002f);
                        float Mvn = satp(fmaf(1e-4f, fmaf(328.25f, sMo,              fmaf(-202.0f, Mv, -10201.0f*Mo)), Mv));
                        float Evn = satp(fmaf(1e-4f, fmaf(328.25f, fmaf(5.5f, u, sE), fmaf(-202.0f, Ev, -10201.0f*Eo)), Ev));
                        Mv_s[q + n] = Mvn;
                        Ev_s[q + n] = Evn;
                        Mv = Mvn; Ev = Evn;
                    }
                }
                __syncthreads();
            }

            // publish Mf(t) + emi(t), then signal peers
            if (isP && act) {
                hist[(t & 63)*HP + n] = M;
                uint32_t ha = smem_u32(&hist[(t & 63)*HP + n]);
                #pragma unroll
                for (uint32_t rk = 1; rk < CLU; ++rk) st_rk_f32(ha, rk, M);
                st_rk_f32(smem_u32(&emi[(t & 1)*208 + n]), 1, E - I);
            }
            __syncthreads();
            if (tid == 0) {
                fence_cluster();
                uint32_t hm = (t & 1) ? mbH1 : mbH0;
                #pragma unroll
                for (uint32_t rk = 1; rk < CLU; ++rk) mbar_arrive_rk(hm, rk);
            }
        }
        if (act) {
            if (isP) {
                float* st = out + OUTD*TB + n*6;
                st[0] = M;  st[1] = E;  st[2] = I;  st[5] = Iv;
            } else {
                float* st = out + OUTD*TB + n*6;
                st[3] = Mv; st[4] = Ev;
            }
        }
    } else {
        // ================= GATHER RANKS 1..7 =================
        __syncthreads();
        CLUSTER_SYNC();
        int r0 = ((int)rank - 1) * 29;
        int r1 = r0 + 29; if (r1 > NN) r1 = NN;
        int w = tid >> 5, l = tid & 31;
        int c0 = 0, c1 = 0;
        uint32_t b2loc0 = smem_u32(&b2[0]);

        for (int r = 0; r < TB; ++r) {
            if (r >= 2) {
                int a = r - 2;
                if (!(a & 1)) { mbar_wait_cl(mbH0, (uint32_t)(c0 & 1)); c0++; }
                else          { mbar_wait_cl(mbH1, (uint32_t)(c1 & 1)); c1++; }
            }
            if (rank == 1 && r >= 2 && tid < 2*OUTD) {
                int rr = r - 2;
                int o = tid >> 1, half = tid & 1;
                const float* lr = g_lmt + o*NN + half*100;
                const float* er = emi + (rr & 1)*208 + half*100;
                float s = 0.0f;
                #pragma unroll 10
                for (int j = 0; j < 100; ++j) s = fmaf(lr[j], er[j], s);
                s += __shfl_xor_sync(0xffffffffu, s, 1);
                if (!half) out[o*TB + rr] = fmaf(5.0f, s, -2.0f);
            }
            for (int row = r0 + w; row < r1; row += 14) {
                const uint2* pp = g_p2 + row*P2SLOT;
                float a = 0.0f;
                #pragma unroll
                for (int e = 0; e < 7; ++e) {
                    uint2 v = pp[e*32 + l];
                    int j = v.y & 0xffff, D = v.y >> 16;
                    a = fmaf(__uint_as_float(v.x), hist[((r - D) & 63)*HP + j], a);
                }
                #pragma unroll
                for (int o = 16; o; o >>= 1) a += __shfl_down_sync(0xffffffffu, a, o);
                if (!l) st_rk_f32(b2loc0 + ((r & 1)*208 + row)*4, 0, a);
            }
            __syncthreads();
            if (tid == 0) { fence_cluster(); mbar_arrive_rk(mbB, 0); }
        }
        if (rank == 1) {
            mbar_wait_cl(mbH0, (uint32_t)(c0 & 1)); c0++;
            if (tid < 2*OUTD) {
                int rr = TB - 2;
                int o = tid >> 1, half = tid & 1;
                const float* lr = g_lmt + o*NN + half*100;
                const float* er = emi + (rr & 1)*208 + half*100;
                float s = 0.0f;
                #pragma unroll 10
                for (int j = 0; j < 100; ++j) s = fmaf(lr[j], er[j], s);
                s += __shfl_xor_sync(0xffffffffu, s, 1);
                if (!half) out[o*TB + rr] = fmaf(5.0f, s, -2.0f);
            }
            mbar_wait_cl(mbH1, (uint32_t)(c1 & 1)); c1++;
            if (tid < 2*OUTD) {
                int rr = TB - 1;
                int o = tid >> 1, half = tid & 1;
                const float* lr = g_lmt + o*NN + half*100;
                const float* er = emi + (rr & 1)*208 + half*100;
                float s = 0.0f;
                #pragma unroll 10
                for (int j = 0; j < 100; ++j) s = fmaf(lr[j], er[j], s);
                s += __shfl_xor_sync(0xffffffffu, s, 1);
                if (!half) out[o*TB + rr] = fmaf(5.0f, s, -2.0f);
            }
        }
    }
    CLUSTER_SYNC();
}

// ---------------- harness entry ----------------
extern "C" void kernel_launch(void* const* d_in, const int* in_sizes, int n_in,
                              void* d_out, int out_size) {
    const float* input    = (const float*)d_in[0];
    const float* noise_in = (const float*)d_in[1];
    const float* hx       = (const float*)d_in[3];
    const float* hE       = (const float*)d_in[4];
    const float* wbb      = (const float*)d_in[5];
    const float* lm       = (const float*)d_in[6];
    const float* sc       = (const float*)d_in[7];
    const int*   dist     = (const int*)d_in[8];
    float*       out      = (float*)d_out;

    cudaFuncSetAttribute(k_main, cudaFuncAttributeMaxDynamicSharedMemorySize, SMEM_BYTES);

    k_trans<<<(TB*HH*NN + 255)/256, 256>>>(input, noise_in);
    k_pre  <<<1, 256>>>(wbb, sc, dist, lm);
    k_main <<<CLU, NTH, SMEM_BYTES>>>(hx, hE, out);
}